// round 7
// baseline (speedup 1.0000x reference)
#include <cuda_runtime.h>

// SCE loss: softmax over C=128, signed per-(class,bin) histogram of
// p - onehot, then sum |.| / (B*C).
// Round 7: 8-lane row groups (16 classes/lane, 4 rows/warp-iter) to amortize
// per-row overhead; running pointers (no per-iter IMAD.WIDE); label "-1" as
// a single predicated shared atomic instead of packed counters.

namespace {
constexpr int kC       = 128;
constexpr int kBins    = 15;
constexpr int kSegs    = kC * kBins;   // 1920
constexpr int kBlocks  = 1184;
constexpr int kThreads = 256;
}

__device__ float    g_seg[kSegs];   // zero at load; last block re-zeroes
__device__ unsigned g_count;        // zero at load; last block re-zeroes

// class of element slot i (i = q*4 + r) for a lane with base column c0:
//   c = c0 + 32*q + r
__device__ __forceinline__ int slot_class(int c0, int i) {
    return c0 + ((i >> 2) << 5) + (i & 3);
}

__global__ void __launch_bounds__(kThreads)
sce_kernel(const float* __restrict__ logits, const int* __restrict__ labels,
           int B, float* __restrict__ out, float scale)
{
    __shared__ float s[kSegs];
    for (int i = threadIdx.x; i < kSegs; i += blockDim.x) s[i] = 0.0f;
    __syncthreads();

    const int lane = threadIdx.x & 31;
    const int wpb  = blockDim.x >> 5;
    const int gw   = blockIdx.x * wpb + (threadIdx.x >> 5);
    const int nw   = gridDim.x * wpb;
    const int g    = lane >> 3;          // row-group 0..3 within warp
    const int c0   = (lane & 7) << 2;    // base column (q=0 slot)

    float bin0[16];
    #pragma unroll
    for (int i = 0; i < 16; i++) bin0[i] = 0.0f;

    // running pointers: this lane's row = row0 + g
    int row0 = gw * 4;
    const float* rp = logits + (size_t)(row0 + g) * kC + c0;
    const int*   lp = labels + row0 + g;
    const size_t rstep = (size_t)nw * 4 * kC;
    const int    lstep = nw * 4;

    for (; row0 + 3 < B; row0 += lstep, rp += rstep, lp += lstep) {
        const int lab = __ldg(lp);

        float e[16];
        #pragma unroll
        for (int q = 0; q < 4; q++) {
            const float4 v = __ldg(reinterpret_cast<const float4*>(rp + 32 * q));
            e[q * 4 + 0] = __expf(v.x);
            e[q * 4 + 1] = __expf(v.y);
            e[q * 4 + 2] = __expf(v.z);
            e[q * 4 + 3] = __expf(v.w);
        }

        const float t0 = (e[0] + e[1])  + (e[2] + e[3]);
        const float t1 = (e[4] + e[5])  + (e[6] + e[7]);
        const float t2 = (e[8] + e[9])  + (e[10] + e[11]);
        const float t3 = (e[12] + e[13]) + (e[14] + e[15]);
        float sm = (t0 + t1) + (t2 + t3);
        #pragma unroll
        for (int o = 4; o > 0; o >>= 1)      // 3-level, within 8-lane group
            sm += __shfl_xor_sync(0xffffffffu, sm, o);

        const float inv    = __fdividef(1.0f, sm);
        const float thresh = sm * (1.0f / 15.0f);   // e > thresh <=> p > 1/15

        #pragma unroll
        for (int i = 0; i < 16; i++)
            bin0[i] = fmaf(e[i], inv, bin0[i]);     // provisional bin 0

        // label -1: exactly one lane per row matches -> predicated ATOMS
        const int  labLocal = lab - c0;
        const bool match = ((unsigned)labLocal < 128u) && ((labLocal & 31) < 4);
        if (match) atomicAdd(&s[lab * kBins], -1.0f);   // provisional bin 0

        float mx = fmaxf(e[0], e[1]);
        #pragma unroll
        for (int i = 2; i < 16; i++) mx = fmaxf(mx, e[i]);
        if (mx > thresh) {                   // rare: fix up p > 1/15 elements
            #pragma unroll
            for (int i = 0; i < 16; i++) {
                if (e[i] > thresh) {
                    const float p = e[i] * inv;
                    int k = __float2int_ru(p * 15.0f) - 1;   // ceil(15p)-1
                    k = min(k, kBins - 1);
                    float add = p;
                    if (match && labLocal == (((i >> 2) << 5) + (i & 3))) {
                        add = p - 1.0f;                  // -1 moves with it
                        atomicAdd(&s[lab * kBins], 1.0f); // cancel provisional
                    }
                    atomicAdd(&s[slot_class(c0, i) * kBins + k], add);
                    bin0[i] -= p;            // undo provisional bin-0 add
                }
            }
        }
    }

    // tail: up to 3 rows, guarded (B % 4 != 0 only)
    if (row0 < B) {
        const int  myrow  = row0 + g;
        const bool active = (myrow < B);
        const int  rr     = active ? myrow : (B - 1);
        const float* trp  = logits + (size_t)rr * kC + c0;
        const int  lab    = __ldg(labels + rr);
        float e[16];
        #pragma unroll
        for (int q = 0; q < 4; q++) {
            const float4 v = __ldg(reinterpret_cast<const float4*>(trp + 32 * q));
            e[q * 4 + 0] = __expf(v.x); e[q * 4 + 1] = __expf(v.y);
            e[q * 4 + 2] = __expf(v.z); e[q * 4 + 3] = __expf(v.w);
        }
        float sm = 0.0f;
        #pragma unroll
        for (int i = 0; i < 16; i++) sm += e[i];
        #pragma unroll
        for (int o = 4; o > 0; o >>= 1)
            sm += __shfl_xor_sync(0xffffffffu, sm, o);
        if (active) {
            const float inv    = __fdividef(1.0f, sm);
            const float thresh = sm * (1.0f / 15.0f);
            const int  labLocal = lab - c0;
            const bool match = ((unsigned)labLocal < 128u) && ((labLocal & 31) < 4);
            if (match) atomicAdd(&s[lab * kBins], -1.0f);
            #pragma unroll
            for (int i = 0; i < 16; i++) {
                const float p = e[i] * inv;
                if (e[i] > thresh) {
                    int k = __float2int_ru(p * 15.0f) - 1;
                    k = min(k, kBins - 1);
                    float add = p;
                    if (match && labLocal == (((i >> 2) << 5) + (i & 3))) {
                        add = p - 1.0f;
                        atomicAdd(&s[lab * kBins], 1.0f);
                    }
                    atomicAdd(&s[slot_class(c0, i) * kBins + k], add);
                } else {
                    bin0[i] += p;
                }
            }
        }
    }

    // flush register accumulators into the block histogram
    #pragma unroll
    for (int i = 0; i < 16; i++)
        atomicAdd(&s[slot_class(c0, i) * kBins], bin0[i]);
    __syncthreads();

    // block histogram -> global
    for (int i = threadIdx.x; i < kSegs; i += blockDim.x) {
        const float v = s[i];
        if (v != 0.0f) atomicAdd(&g_seg[i], v);
    }

    // last-block finalize
    __shared__ bool isLast;
    __threadfence();
    if (threadIdx.x == 0)
        isLast = (atomicAdd(&g_count, 1u) == (unsigned)gridDim.x - 1u);
    __syncthreads();
    if (!isLast) return;

    __shared__ float red[32];
    float acc = 0.0f;
    for (int i = threadIdx.x; i < kSegs; i += blockDim.x) {
        acc += fabsf(__ldcg(&g_seg[i]));
        g_seg[i] = 0.0f;                   // reset for next replay
    }
    #pragma unroll
    for (int o = 16; o > 0; o >>= 1)
        acc += __shfl_xor_sync(0xffffffffu, acc, o);
    const int w = threadIdx.x >> 5;
    if (lane == 0) red[w] = acc;
    __syncthreads();
    if (w == 0) {
        const int nwarps = blockDim.x >> 5;
        acc = (lane < nwarps) ? red[lane] : 0.0f;
        #pragma unroll
        for (int o = 16; o > 0; o >>= 1)
            acc += __shfl_xor_sync(0xffffffffu, acc, o);
        if (threadIdx.x == 0) {
            out[0]  = acc * scale;
            g_count = 0u;                  // reset for next replay
        }
    }
}

extern "C" void kernel_launch(void* const* d_in, const int* in_sizes, int n_in,
                              void* d_out, int out_size) {
    const float* logits = (const float*)d_in[0];
    const int*   labels = (const int*)d_in[1];
    const int B = in_sizes[1];
    const float scale = 1.0f / ((float)B * (float)kC);
    sce_kernel<<<kBlocks, kThreads>>>(logits, labels, B, (float*)d_out, scale);
}

// round 8
// speedup vs baseline: 1.0988x; 1.0988x over previous
#include <cuda_runtime.h>

// SCE loss: softmax over C=128, signed per-(class,bin) histogram of
// p - onehot, then sum |.| / (B*C).
// Round 8: R6 half-warp structure (2 rows/warp-iter, 8 classes/lane,
// <=32 regs) with: fully-coalesced split layout (lane owns [4L..4L+3] and
// [64+4L..64+4L+3] -> every LDG.128 contiguous), running pointers, and the
// label -1 as a single predicated shared atomic.

namespace {
constexpr int kC       = 128;
constexpr int kBins    = 15;
constexpr int kSegs    = kC * kBins;   // 1920
constexpr int kBlocks  = 1184;
constexpr int kThreads = 256;
}

__device__ float    g_seg[kSegs];   // zero at load; last block re-zeroes
__device__ unsigned g_count;        // zero at load; last block re-zeroes

__global__ void __launch_bounds__(kThreads, 8)
sce_kernel(const float* __restrict__ logits, const int* __restrict__ labels,
           int B, float* __restrict__ out, float scale)
{
    __shared__ float s[kSegs];
    for (int i = threadIdx.x; i < kSegs; i += blockDim.x) s[i] = 0.0f;
    __syncthreads();

    const int lane = threadIdx.x & 31;
    const int wpb  = blockDim.x >> 5;
    const int gw   = blockIdx.x * wpb + (threadIdx.x >> 5);
    const int nw   = gridDim.x * wpb;
    const int h    = lane >> 4;          // which row of the pair
    const int L    = lane & 15;
    const int c0   = L << 2;             // classes c0..c0+3 and 64+c0..64+c0+3

    float bin0[8] = {0,0,0,0,0,0,0,0};

    int row0 = gw * 2;
    const float* rp = logits + (size_t)(row0 + h) * kC + c0;
    const int*   lp = labels + row0 + h;
    const size_t rstep = (size_t)nw * 2 * kC;
    const int    lstep = nw * 2;

    for (; row0 + 1 < B; row0 += lstep, rp += rstep, lp += lstep) {
        const int lab = __ldg(lp);
        // both LDG.128s fully coalesced: 16 lanes x 16B contiguous per row
        const float4 va = __ldg(reinterpret_cast<const float4*>(rp));
        const float4 vb = __ldg(reinterpret_cast<const float4*>(rp + 64));

        float e[8];
        e[0] = __expf(va.x); e[1] = __expf(va.y);
        e[2] = __expf(va.z); e[3] = __expf(va.w);
        e[4] = __expf(vb.x); e[5] = __expf(vb.y);
        e[6] = __expf(vb.z); e[7] = __expf(vb.w);

        float sm = ((e[0] + e[1]) + (e[2] + e[3]))
                 + ((e[4] + e[5]) + (e[6] + e[7]));
        #pragma unroll
        for (int o = 8; o > 0; o >>= 1)      // 4-level, within 16-lane half
            sm += __shfl_xor_sync(0xffffffffu, sm, o);

        const float inv    = __fdividef(1.0f, sm);
        const float thresh = sm * (1.0f / 15.0f);   // e > thresh <=> p > 1/15

        #pragma unroll
        for (int j = 0; j < 8; j++)
            bin0[j] = fmaf(e[j], inv, bin0[j]);     // provisional bin 0

        // label -1: exactly one lane per row matches (predicated ATOMS)
        const int  r    = lab & 63;
        const int  jlab = (lab >> 6 << 2) | (r & 3);   // slot if owned
        const bool match = (L == (r >> 2));
        if (match) atomicAdd(&s[lab * kBins], -1.0f);  // provisional bin 0

        const float m01 = fmaxf(fmaxf(e[0], e[1]), fmaxf(e[2], e[3]));
        const float m23 = fmaxf(fmaxf(e[4], e[5]), fmaxf(e[6], e[7]));
        if (fmaxf(m01, m23) > thresh) {      // rare: fix up p > 1/15 elements
            #pragma unroll
            for (int j = 0; j < 8; j++) {
                if (e[j] > thresh) {
                    const float p = e[j] * inv;
                    int k = __float2int_ru(p * 15.0f) - 1;   // ceil(15p)-1
                    k = min(k, kBins - 1);
                    float add = p;
                    if (match && j == jlab) {
                        add = p - 1.0f;                   // -1 moves with it
                        atomicAdd(&s[lab * kBins], 1.0f); // cancel provisional
                    }
                    const int cls = (j < 4) ? (c0 + j) : (64 + c0 + j - 4);
                    atomicAdd(&s[cls * kBins + k], add);
                    bin0[j] -= p;            // undo provisional bin-0 add
                }
            }
        }
    }

    // odd-B tail: one row, processed by the h==0 half (h==1 joins shuffles)
    if (row0 < B) {
        const float* trp = logits + (size_t)row0 * kC + c0;
        const int lab = __ldg(labels + row0);
        float e[8];
        const float4 va = __ldg(reinterpret_cast<const float4*>(trp));
        const float4 vb = __ldg(reinterpret_cast<const float4*>(trp + 64));
        e[0] = __expf(va.x); e[1] = __expf(va.y);
        e[2] = __expf(va.z); e[3] = __expf(va.w);
        e[4] = __expf(vb.x); e[5] = __expf(vb.y);
        e[6] = __expf(vb.z); e[7] = __expf(vb.w);
        float sm = 0.0f;
        #pragma unroll
        for (int j = 0; j < 8; j++) sm += e[j];
        #pragma unroll
        for (int o = 8; o > 0; o >>= 1)
            sm += __shfl_xor_sync(0xffffffffu, sm, o);
        if (h == 0) {
            const float inv    = __fdividef(1.0f, sm);
            const float thresh = sm * (1.0f / 15.0f);
            const int  r    = lab & 63;
            const int  jlab = (lab >> 6 << 2) | (r & 3);
            const bool match = (L == (r >> 2));
            if (match) atomicAdd(&s[lab * kBins], -1.0f);
            #pragma unroll
            for (int j = 0; j < 8; j++) {
                const float p = e[j] * inv;
                if (e[j] > thresh) {
                    int k = __float2int_ru(p * 15.0f) - 1;
                    k = min(k, kBins - 1);
                    float add = p;
                    if (match && j == jlab) {
                        add = p - 1.0f;
                        atomicAdd(&s[lab * kBins], 1.0f);
                    }
                    const int cls = (j < 4) ? (c0 + j) : (64 + c0 + j - 4);
                    atomicAdd(&s[cls * kBins + k], add);
                } else {
                    bin0[j] += p;
                }
            }
        }
    }

    // flush register accumulators into the block histogram
    #pragma unroll
    for (int j = 0; j < 8; j++) {
        const int cls = (j < 4) ? (c0 + j) : (64 + c0 + j - 4);
        atomicAdd(&s[cls * kBins], bin0[j]);
    }
    __syncthreads();

    // block histogram -> global
    for (int i = threadIdx.x; i < kSegs; i += blockDim.x) {
        const float v = s[i];
        if (v != 0.0f) atomicAdd(&g_seg[i], v);
    }

    // last-block finalize
    __shared__ bool isLast;
    __threadfence();
    if (threadIdx.x == 0)
        isLast = (atomicAdd(&g_count, 1u) == (unsigned)gridDim.x - 1u);
    __syncthreads();
    if (!isLast) return;

    __shared__ float red[32];
    float acc = 0.0f;
    for (int i = threadIdx.x; i < kSegs; i += blockDim.x) {
        acc += fabsf(__ldcg(&g_seg[i]));
        g_seg[i] = 0.0f;                   // reset for next replay
    }
    #pragma unroll
    for (int o = 16; o > 0; o >>= 1)
        acc += __shfl_xor_sync(0xffffffffu, acc, o);
    const int w = threadIdx.x >> 5;
    if (lane == 0) red[w] = acc;
    __syncthreads();
    if (w == 0) {
        const int nwarps = blockDim.x >> 5;
        acc = (lane < nwarps) ? red[lane] : 0.0f;
        #pragma unroll
        for (int o = 16; o > 0; o >>= 1)
            acc += __shfl_xor_sync(0xffffffffu, acc, o);
        if (threadIdx.x == 0) {
            out[0]  = acc * scale;
            g_count = 0u;                  // reset for next replay
        }
    }
}

extern "C" void kernel_launch(void* const* d_in, const int* in_sizes, int n_in,
                              void* d_out, int out_size) {
    const float* logits = (const float*)d_in[0];
    const int*   labels = (const int*)d_in[1];
    const int B = in_sizes[1];
    const float scale = 1.0f / ((float)B * (float)kC);
    sce_kernel<<<kBlocks, kThreads>>>(logits, labels, B, (float*)d_out, scale);
}

// round 9
// speedup vs baseline: 1.1033x; 1.0041x over previous
#include <cuda_runtime.h>

// SCE loss: softmax over C=128, signed per-(class,bin) histogram of
// p - onehot, then sum |.| / (B*C).
// Round 9: three-tier binning. Register bin0 (p<=1/15) and bin1
// (1/15<p<=2/15) with branchless select; slow path only for p>2/15
// (warp-level P ~10% instead of ~65%). Label -1 picks bin 0/1 via a SEL
// mux of the label element's exp; labels with p>2/15 handled entirely in
// the slow path (no cancel atomic).

namespace {
constexpr int kC       = 128;
constexpr int kBins    = 15;
constexpr int kSegs    = kC * kBins;   // 1920
constexpr int kBlocks  = 888;          // 6 blocks/SM x 148 SMs, exact wave
constexpr int kThreads = 256;
}

__device__ float    g_seg[kSegs];   // zero at load; last block re-zeroes
__device__ unsigned g_count;        // zero at load; last block re-zeroes

__global__ void __launch_bounds__(kThreads, 6)
sce_kernel(const float* __restrict__ logits, const int* __restrict__ labels,
           int B, float* __restrict__ out, float scale)
{
    __shared__ float s[kSegs];
    for (int i = threadIdx.x; i < kSegs; i += blockDim.x) s[i] = 0.0f;
    __syncthreads();

    const int lane = threadIdx.x & 31;
    const int wpb  = blockDim.x >> 5;
    const int gw   = blockIdx.x * wpb + (threadIdx.x >> 5);
    const int nw   = gridDim.x * wpb;
    const int h    = lane >> 4;          // which row of the pair
    const int L    = lane & 15;
    const int c0   = L << 2;             // classes c0..c0+3 and 64+c0..64+c0+3

    float bin0[8] = {0,0,0,0,0,0,0,0};   // p <= 1/15
    float bin1[8] = {0,0,0,0,0,0,0,0};   // 1/15 < p <= 2/15 (+ provisional >2/15)

    int row0 = gw * 2;
    const float* rp = logits + (size_t)(row0 + h) * kC + c0;
    const int*   lp = labels + row0 + h;
    const size_t rstep = (size_t)nw * 2 * kC;
    const int    lstep = nw * 2;

    for (; row0 + 1 < B; row0 += lstep, rp += rstep, lp += lstep) {
        const int lab = __ldg(lp);
        const float4 va = __ldg(reinterpret_cast<const float4*>(rp));
        const float4 vb = __ldg(reinterpret_cast<const float4*>(rp + 64));

        float e[8];
        e[0] = __expf(va.x); e[1] = __expf(va.y);
        e[2] = __expf(va.z); e[3] = __expf(va.w);
        e[4] = __expf(vb.x); e[5] = __expf(vb.y);
        e[6] = __expf(vb.z); e[7] = __expf(vb.w);

        float sm = ((e[0] + e[1]) + (e[2] + e[3]))
                 + ((e[4] + e[5]) + (e[6] + e[7]));
        #pragma unroll
        for (int o = 8; o > 0; o >>= 1)
            sm += __shfl_xor_sync(0xffffffffu, sm, o);

        const float inv = __fdividef(1.0f, sm);
        const float t1  = sm * (1.0f / 15.0f);   // e > t1 <=> p > 1/15
        const float t2  = sm * (2.0f / 15.0f);   // e > t2 <=> p > 2/15

        // branchless two-register binning
        #pragma unroll
        for (int j = 0; j < 8; j++) {
            if (e[j] > t1) bin1[j] = fmaf(e[j], inv, bin1[j]);
            else           bin0[j] = fmaf(e[j], inv, bin0[j]);
        }

        // label -1: owner lane selects the label element's exp via SEL mux
        const bool match = (L == ((lab & 63) >> 2));
        const bool b0 = (lab & 1), b1 = (lab & 2), b2 = (lab & 64);
        const float m0 = b0 ? e[1] : e[0];
        const float m1 = b0 ? e[3] : e[2];
        const float m2 = b0 ? e[5] : e[4];
        const float m3 = b0 ? e[7] : e[6];
        const float n0 = b1 ? m1 : m0;
        const float n1 = b1 ? m3 : m2;
        const float esel = b2 ? n1 : n0;
        if (match && esel <= t2)             // p>2/15 labels: slow path owns -1
            atomicAdd(&s[lab * kBins + (esel > t1 ? 1 : 0)], -1.0f);

        float mx = fmaxf(fmaxf(fmaxf(e[0], e[1]), fmaxf(e[2], e[3])),
                         fmaxf(fmaxf(e[4], e[5]), fmaxf(e[6], e[7])));
        if (mx > t2) {                       // rare now (~10% of warp-iters)
            const int jlab = ((lab >> 6) << 2) | (lab & 3);
            #pragma unroll
            for (int j = 0; j < 8; j++) {
                if (e[j] > t2) {
                    const float p = e[j] * inv;
                    int k = __float2int_ru(p * 15.0f) - 1;   // >= 2 here
                    k = min(k, kBins - 1);
                    const bool isl = match && (j == jlab);
                    const float add = isl ? (p - 1.0f) : p;
                    const int cls = (j < 4) ? (c0 + j) : (64 + c0 + j - 4);
                    atomicAdd(&s[cls * kBins + k], add);
                    bin1[j] -= p;            // it was provisionally in bin1
                }
            }
        }
    }

    // odd-B tail: one row, h==0 half does the work (h==1 joins shuffles)
    if (row0 < B) {
        const float* trp = logits + (size_t)row0 * kC + c0;
        const int lab = __ldg(labels + row0);
        const float4 va = __ldg(reinterpret_cast<const float4*>(trp));
        const float4 vb = __ldg(reinterpret_cast<const float4*>(trp + 64));
        float e[8];
        e[0] = __expf(va.x); e[1] = __expf(va.y);
        e[2] = __expf(va.z); e[3] = __expf(va.w);
        e[4] = __expf(vb.x); e[5] = __expf(vb.y);
        e[6] = __expf(vb.z); e[7] = __expf(vb.w);
        float sm = 0.0f;
        #pragma unroll
        for (int j = 0; j < 8; j++) sm += e[j];
        #pragma unroll
        for (int o = 8; o > 0; o >>= 1)
            sm += __shfl_xor_sync(0xffffffffu, sm, o);
        if (h == 0) {
            const float inv = __fdividef(1.0f, sm);
            const bool match = (L == ((lab & 63) >> 2));
            const int  jlab  = ((lab >> 6) << 2) | (lab & 3);
            #pragma unroll
            for (int j = 0; j < 8; j++) {
                const float p = e[j] * inv;
                int k = __float2int_ru(p * 15.0f) - 1;
                k = max(min(k, kBins - 1), 0);
                const bool isl = match && (j == jlab);
                const float add = isl ? (p - 1.0f) : p;
                const int cls = (j < 4) ? (c0 + j) : (64 + c0 + j - 4);
                atomicAdd(&s[cls * kBins + k], add);
            }
        }
    }

    // flush register accumulators into the block histogram
    #pragma unroll
    for (int j = 0; j < 8; j++) {
        const int cls = (j < 4) ? (c0 + j) : (64 + c0 + j - 4);
        atomicAdd(&s[cls * kBins + 0], bin0[j]);
        atomicAdd(&s[cls * kBins + 1], bin1[j]);
    }
    __syncthreads();

    // block histogram -> global
    for (int i = threadIdx.x; i < kSegs; i += blockDim.x) {
        const float v = s[i];
        if (v != 0.0f) atomicAdd(&g_seg[i], v);
    }

    // last-block finalize
    __shared__ bool isLast;
    __threadfence();
    if (threadIdx.x == 0)
        isLast = (atomicAdd(&g_count, 1u) == (unsigned)gridDim.x - 1u);
    __syncthreads();
    if (!isLast) return;

    __shared__ float red[32];
    float acc = 0.0f;
    for (int i = threadIdx.x; i < kSegs; i += blockDim.x) {
        acc += fabsf(__ldcg(&g_seg[i]));
        g_seg[i] = 0.0f;                   // reset for next replay
    }
    #pragma unroll
    for (int o = 16; o > 0; o >>= 1)
        acc += __shfl_xor_sync(0xffffffffu, acc, o);
    const int w = threadIdx.x >> 5;
    if (lane == 0) red[w] = acc;
    __syncthreads();
    if (w == 0) {
        const int nwarps = blockDim.x >> 5;
        acc = (lane < nwarps) ? red[lane] : 0.0f;
        #pragma unroll
        for (int o = 16; o > 0; o >>= 1)
            acc += __shfl_xor_sync(0xffffffffu, acc, o);
        if (threadIdx.x == 0) {
            out[0]  = acc * scale;
            g_count = 0u;                  // reset for next replay
        }
    }
}

extern "C" void kernel_launch(void* const* d_in, const int* in_sizes, int n_in,
                              void* d_out, int out_size) {
    const float* logits = (const float*)d_in[0];
    const int*   labels = (const int*)d_in[1];
    const int B = in_sizes[1];
    const float scale = 1.0f / ((float)B * (float)kC);
    sce_kernel<<<kBlocks, kThreads>>>(logits, labels, B, (float*)d_out, scale);
}